// round 1
// baseline (speedup 1.0000x reference)
#include <cuda_runtime.h>
#include <cuda_fp16.h>

// Swin window attention, fully fused: one CTA per 8x8 window.
// x:[8,64,256,256] f32. LN -> QKV(fp16 mma) -> per-head softmax(QK^T+bias) -> AV -> proj -> x + s*out.

#define NWIN   8192
#define TPB    256

// smem layout (bytes)
#define OFF_XF   0        // float [64][68]   17408
#define OFF_XN   17408    // half  [64][72]    9216  (reused as attn-out AO)
#define OFF_WQ   26624    // half  [192][72]  27648  (reused for proj_w [64][72])
#define OFF_QKV  54272    // half  [64][200]  25600
#define OFF_RPB  79872    // float [225][4]    3600
#define OFF_NW   83472    // float [64]
#define OFF_NB   83728    // float [64]
#define OFF_SC   83984    // float
#define SMEM_BYTES 84000

__device__ __half g_qkvw[192 * 64];
__device__ __half g_projw[64 * 64];

__global__ void prep_weights(const float* __restrict__ qw, const float* __restrict__ pw) {
    int i = blockIdx.x * blockDim.x + threadIdx.x;
    if (i < 192 * 64) g_qkvw[i] = __float2half(qw[i]);
    if (i < 64 * 64)  g_projw[i] = __float2half(pw[i]);
}

__device__ __forceinline__ unsigned saddr(const void* p) {
    return (unsigned)__cvta_generic_to_shared(p);
}
__device__ __forceinline__ void ldsm_x4(unsigned a, unsigned& r0, unsigned& r1, unsigned& r2, unsigned& r3) {
    asm volatile("ldmatrix.sync.aligned.m8n8.x4.shared.b16 {%0,%1,%2,%3}, [%4];"
                 : "=r"(r0), "=r"(r1), "=r"(r2), "=r"(r3) : "r"(a));
}
__device__ __forceinline__ void ldsm_x2(unsigned a, unsigned& r0, unsigned& r1) {
    asm volatile("ldmatrix.sync.aligned.m8n8.x2.shared.b16 {%0,%1}, [%2];"
                 : "=r"(r0), "=r"(r1) : "r"(a));
}
__device__ __forceinline__ void ldsm_x2t(unsigned a, unsigned& r0, unsigned& r1) {
    asm volatile("ldmatrix.sync.aligned.m8n8.x2.trans.shared.b16 {%0,%1}, [%2];"
                 : "=r"(r0), "=r"(r1) : "r"(a));
}
__device__ __forceinline__ void mma16816(float c[4], unsigned a0, unsigned a1, unsigned a2, unsigned a3,
                                         unsigned b0, unsigned b1) {
    asm volatile("mma.sync.aligned.m16n8k16.row.col.f32.f16.f16.f32 "
                 "{%0,%1,%2,%3}, {%4,%5,%6,%7}, {%8,%9}, {%0,%1,%2,%3};"
                 : "+f"(c[0]), "+f"(c[1]), "+f"(c[2]), "+f"(c[3])
                 : "r"(a0), "r"(a1), "r"(a2), "r"(a3), "r"(b0), "r"(b1));
}
__device__ __forceinline__ unsigned packh2(float lo, float hi) {
    __half2 h = __floats2half2_rn(lo, hi);
    return *reinterpret_cast<unsigned*>(&h);
}

__global__ __launch_bounds__(256, 2)
void ewa_kernel(const float* __restrict__ x,
                const float* __restrict__ nw, const float* __restrict__ nb,
                const float* __restrict__ ascale, const float* __restrict__ rpb,
                float* __restrict__ out) {
    extern __shared__ char smem[];
    float*  Xf  = (float*)(smem + OFF_XF);    // [64][68]
    __half* XN  = (__half*)(smem + OFF_XN);   // [64][72] (later AO)
    __half* Wq  = (__half*)(smem + OFF_WQ);   // [192][72] (later proj_w [64][72])
    __half* QKV = (__half*)(smem + OFF_QKV);  // [64][200]
    float*  RPB = (float*)(smem + OFF_RPB);   // [225][4]
    float*  SNW = (float*)(smem + OFF_NW);
    float*  SNB = (float*)(smem + OFF_NB);
    float*  SSC = (float*)(smem + OFF_SC);

    const int tid  = threadIdx.x;
    const int lane = tid & 31;
    const int warp = tid >> 5;
    const int g    = lane >> 2;
    const int tig  = lane & 3;

    const int win = blockIdx.x;
    const int b   = win >> 10;
    const int rem = win & 1023;
    const int wy  = rem >> 5;
    const int wx  = rem & 31;

    // ---- Phase 1: load window + weights + params into smem ----
    #pragma unroll
    for (int i = tid; i < 512; i += TPB) {             // (c,y) rows of 8 floats
        int c = i >> 3, y = i & 7;
        const float* p = x + (((b * 64 + c) * 256) + (wy * 8 + y)) * 256 + wx * 8;
        float4 v0 = *(const float4*)p;
        float4 v1 = *(const float4*)(p + 4);
        int t = y * 8;
        Xf[(t + 0) * 68 + c] = v0.x; Xf[(t + 1) * 68 + c] = v0.y;
        Xf[(t + 2) * 68 + c] = v0.z; Xf[(t + 3) * 68 + c] = v0.w;
        Xf[(t + 4) * 68 + c] = v1.x; Xf[(t + 5) * 68 + c] = v1.y;
        Xf[(t + 6) * 68 + c] = v1.z; Xf[(t + 7) * 68 + c] = v1.w;
    }
    #pragma unroll
    for (int i = tid; i < 1536; i += TPB) {            // qkv_w fp16: 192 rows x 8 int4-chunks
        int row = i >> 3, ck = i & 7;
        *(int4*)(Wq + row * 72 + ck * 8) = *(const int4*)(g_qkvw + row * 64 + ck * 8);
    }
    for (int i = tid; i < 900; i += TPB) RPB[i] = rpb[i];
    if (tid < 64) { SNW[tid] = nw[tid]; SNB[tid] = nb[tid]; }
    if (tid == 0) SSC[0] = ascale[0];
    __syncthreads();

    // ---- Phase 2: LayerNorm over channels (4 threads per token) ----
    {
        int token = tid >> 2, q = tid & 3;
        const float* row = Xf + token * 68 + q * 16;
        float s = 0.f, ss = 0.f;
        #pragma unroll
        for (int i = 0; i < 16; i++) { float v = row[i]; s += v; ss += v * v; }
        s  += __shfl_xor_sync(0xffffffffu, s, 1);  ss += __shfl_xor_sync(0xffffffffu, ss, 1);
        s  += __shfl_xor_sync(0xffffffffu, s, 2);  ss += __shfl_xor_sync(0xffffffffu, ss, 2);
        float mu   = s * (1.f / 64.f);
        float var  = ss * (1.f / 64.f) - mu * mu;
        float rstd = rsqrtf(var + 1e-5f);
        __half* dst = XN + token * 72 + q * 16;
        #pragma unroll
        for (int i = 0; i < 16; i++) {
            int c = q * 16 + i;
            dst[i] = __float2half((row[i] - mu) * rstd * SNW[c] + SNB[c]);
        }
    }
    __syncthreads();

    // ---- Phase 3: QKV GEMM  [64,64]x[64,192] -> QKV smem (q pre-scaled by hd^-0.5) ----
    {
        const int m0 = (warp & 3) * 16;
        const int n0 = (warp >> 2) * 96;
        float acc[12][4];
        #pragma unroll
        for (int j = 0; j < 12; j++) { acc[j][0] = acc[j][1] = acc[j][2] = acc[j][3] = 0.f; }
        const int l2 = lane & 15;
        #pragma unroll
        for (int kt = 0; kt < 4; kt++) {
            int k0 = kt * 16;
            unsigned a0, a1, a2, a3;
            ldsm_x4(saddr(XN + (m0 + (lane & 15)) * 72 + k0 + (lane >> 4) * 8), a0, a1, a2, a3);
            #pragma unroll
            for (int j = 0; j < 12; j++) {
                int n = n0 + j * 8;
                unsigned b0, b1;
                ldsm_x2(saddr(Wq + (n + (l2 & 7)) * 72 + k0 + (l2 >> 3) * 8), b0, b1);
                mma16816(acc[j], a0, a1, a2, a3, b0, b1);
            }
        }
        #pragma unroll
        for (int j = 0; j < 12; j++) {
            int col = n0 + j * 8 + tig * 2;
            float sc = (col < 64) ? 0.25f : 1.0f;   // hd^-0.5 folded into q
            *(unsigned*)(QKV + (m0 + g) * 200 + col)     = packh2(acc[j][0] * sc, acc[j][1] * sc);
            *(unsigned*)(QKV + (m0 + g + 8) * 200 + col) = packh2(acc[j][2] * sc, acc[j][3] * sc);
        }
    }
    __syncthreads();

    // stage proj_w into (now free) Wq region; consumed after next sync
    #pragma unroll
    for (int i = tid; i < 512; i += TPB) {
        int row = i >> 3, ck = i & 7;
        *(int4*)(Wq + row * 72 + ck * 8) = *(const int4*)(g_projw + row * 64 + ck * 8);
    }

    // ---- Phase 4: attention per head. warp -> (head = warp>>1, rows m0 = (warp&1)*32) ----
    {
        const int h  = warp >> 1;
        const int m0 = (warp & 1) * 32;
        const int l2 = lane & 15;

        unsigned qa[2][4];
        #pragma unroll
        for (int mt = 0; mt < 2; mt++)
            ldsm_x4(saddr(QKV + (m0 + mt * 16 + (lane & 15)) * 200 + h * 16 + (lane >> 4) * 8),
                    qa[mt][0], qa[mt][1], qa[mt][2], qa[mt][3]);

        float s[2][8][4];
        #pragma unroll
        for (int mt = 0; mt < 2; mt++)
            #pragma unroll
            for (int j = 0; j < 8; j++)
                { s[mt][j][0] = s[mt][j][1] = s[mt][j][2] = s[mt][j][3] = 0.f; }

        #pragma unroll
        for (int j = 0; j < 8; j++) {
            int n = j * 8;
            unsigned b0, b1;
            ldsm_x2(saddr(QKV + (n + (l2 & 7)) * 200 + 64 + h * 16 + (l2 >> 3) * 8), b0, b1);
            mma16816(s[0][j], qa[0][0], qa[0][1], qa[0][2], qa[0][3], b0, b1);
            mma16816(s[1][j], qa[1][0], qa[1][1], qa[1][2], qa[1][3], b0, b1);
        }

        // bias + softmax (rows owned by 4 consecutive lanes)
        float rmax[2][2] = {{-1e30f, -1e30f}, {-1e30f, -1e30f}};
        #pragma unroll
        for (int mt = 0; mt < 2; mt++)
            #pragma unroll
            for (int j = 0; j < 8; j++)
                #pragma unroll
                for (int e = 0; e < 4; e++) {
                    int rr = m0 + mt * 16 + g + (e >> 1) * 8;
                    int cc = j * 8 + tig * 2 + (e & 1);
                    int dy = (rr >> 3) - (cc >> 3), dx = (rr & 7) - (cc & 7);
                    float v = s[mt][j][e] + RPB[((dy + 7) * 15 + (dx + 7)) * 4 + h];
                    s[mt][j][e] = v;
                    rmax[mt][e >> 1] = fmaxf(rmax[mt][e >> 1], v);
                }
        #pragma unroll
        for (int mt = 0; mt < 2; mt++)
            #pragma unroll
            for (int hh = 0; hh < 2; hh++) {
                float m_ = rmax[mt][hh];
                m_ = fmaxf(m_, __shfl_xor_sync(0xffffffffu, m_, 1));
                m_ = fmaxf(m_, __shfl_xor_sync(0xffffffffu, m_, 2));
                rmax[mt][hh] = m_;
            }
        float rsum[2][2] = {{0.f, 0.f}, {0.f, 0.f}};
        #pragma unroll
        for (int mt = 0; mt < 2; mt++)
            #pragma unroll
            for (int j = 0; j < 8; j++)
                #pragma unroll
                for (int e = 0; e < 4; e++) {
                    float p = __expf(s[mt][j][e] - rmax[mt][e >> 1]);
                    s[mt][j][e] = p;
                    rsum[mt][e >> 1] += p;
                }
        float inv[2][2];
        #pragma unroll
        for (int mt = 0; mt < 2; mt++)
            #pragma unroll
            for (int hh = 0; hh < 2; hh++) {
                float l = rsum[mt][hh];
                l += __shfl_xor_sync(0xffffffffu, l, 1);
                l += __shfl_xor_sync(0xffffffffu, l, 2);
                inv[mt][hh] = 1.f / l;
            }

        // convert P to A-fragments in registers (no smem round trip)
        unsigned pa[2][4][4];
        #pragma unroll
        for (int mt = 0; mt < 2; mt++)
            #pragma unroll
            for (int kt = 0; kt < 4; kt++) {
                float i0 = inv[mt][0], i1 = inv[mt][1];
                pa[mt][kt][0] = packh2(s[mt][2 * kt][0] * i0,     s[mt][2 * kt][1] * i0);
                pa[mt][kt][1] = packh2(s[mt][2 * kt][2] * i1,     s[mt][2 * kt][3] * i1);
                pa[mt][kt][2] = packh2(s[mt][2 * kt + 1][0] * i0, s[mt][2 * kt + 1][1] * i0);
                pa[mt][kt][3] = packh2(s[mt][2 * kt + 1][2] * i1, s[mt][2 * kt + 1][3] * i1);
            }

        // AV: out[32,16] per warp, V loaded via ldmatrix.trans from [token][hd]
        float o[2][2][4];
        #pragma unroll
        for (int mt = 0; mt < 2; mt++)
            #pragma unroll
            for (int nt = 0; nt < 2; nt++)
                { o[mt][nt][0] = o[mt][nt][1] = o[mt][nt][2] = o[mt][nt][3] = 0.f; }
        #pragma unroll
        for (int kt = 0; kt < 4; kt++)
            #pragma unroll
            for (int nt = 0; nt < 2; nt++) {
                unsigned b0, b1;
                ldsm_x2t(saddr(QKV + (kt * 16 + (lane & 15)) * 200 + 128 + h * 16 + nt * 8), b0, b1);
                mma16816(o[0][nt], pa[0][kt][0], pa[0][kt][1], pa[0][kt][2], pa[0][kt][3], b0, b1);
                mma16816(o[1][nt], pa[1][kt][0], pa[1][kt][1], pa[1][kt][2], pa[1][kt][3], b0, b1);
            }

        // write attention output (heads concat) into AO = XN region
        #pragma unroll
        for (int mt = 0; mt < 2; mt++)
            #pragma unroll
            for (int nt = 0; nt < 2; nt++) {
                int row = m0 + mt * 16 + g;
                int col = h * 16 + nt * 8 + tig * 2;
                *(unsigned*)(XN + row * 72 + col)       = packh2(o[mt][nt][0], o[mt][nt][1]);
                *(unsigned*)(XN + (row + 8) * 72 + col) = packh2(o[mt][nt][2], o[mt][nt][3]);
            }
    }
    __syncthreads();

    // ---- Phase 5: proj GEMM [64,64]x[64,64] + residual + write out ----
    {
        const int m0 = (warp >> 1) * 16;
        const int n0 = (warp & 1) * 32;
        const int l2 = lane & 15;
        float acc[4][4];
        #pragma unroll
        for (int j = 0; j < 4; j++) { acc[j][0] = acc[j][1] = acc[j][2] = acc[j][3] = 0.f; }
        #pragma unroll
        for (int kt = 0; kt < 4; kt++) {
            int k0 = kt * 16;
            unsigned a0, a1, a2, a3;
            ldsm_x4(saddr(XN + (m0 + (lane & 15)) * 72 + k0 + (lane >> 4) * 8), a0, a1, a2, a3);
            #pragma unroll
            for (int j = 0; j < 4; j++) {
                int n = n0 + j * 8;
                unsigned b0, b1;
                ldsm_x2(saddr(Wq + (n + (l2 & 7)) * 72 + k0 + (l2 >> 3) * 8), b0, b1);
                mma16816(acc[j], a0, a1, a2, a3, b0, b1);
            }
        }
        float ssc = SSC[0];
        #pragma unroll
        for (int j = 0; j < 4; j++)
            #pragma unroll
            for (int e = 0; e < 4; e++) {
                int row = m0 + g + (e >> 1) * 8;            // token
                int ch  = n0 + j * 8 + tig * 2 + (e & 1);   // channel
                float val = Xf[row * 68 + ch] + ssc * acc[j][e];
                out[(((b * 64 + ch) * 256) + (wy * 8 + (row >> 3))) * 256 + wx * 8 + (row & 7)] = val;
            }
    }
}

extern "C" void kernel_launch(void* const* d_in, const int* in_sizes, int n_in,
                              void* d_out, int out_size) {
    const float* x  = (const float*)d_in[0];
    const float* nw = (const float*)d_in[1];
    const float* nb = (const float*)d_in[2];
    const float* qw = (const float*)d_in[3];
    const float* pw = (const float*)d_in[4];
    const float* sc = (const float*)d_in[5];
    const float* rp = (const float*)d_in[6];
    float* out = (float*)d_out;

    cudaFuncSetAttribute(ewa_kernel, cudaFuncAttributeMaxDynamicSharedMemorySize, SMEM_BYTES);

    prep_weights<<<48, 256>>>(qw, pw);
    ewa_kernel<<<NWIN, TPB, SMEM_BYTES>>>(x, nw, nb, sc, rp, out);
}

// round 2
// speedup vs baseline: 1.4975x; 1.4975x over previous
#include <cuda_runtime.h>
#include <cuda_fp16.h>

// Swin window attention, fully fused: one CTA per 8x8 window, 3 CTAs/SM.
// LN folded into weights; rel-pos bias pre-baked into MMA-fragment layout.

#define NWIN   8192
#define TPB    256

// smem layout (bytes)
#define OFF_XN   0        // half [64][72]   9216   (LN output Z; later attn-out AO)
#define OFF_WQ   9216     // half [192][72] 27648   (qkv weights; later proj_w [64][72])
#define OFF_QKV  36864    // half [64][200] 25600
#define SMEM_BYTES 62464

__device__ __half g_qkvw[192 * 64];   // qkv_w * norm_w (folded)
__device__ __half g_projw[64 * 64];
__device__ float  g_qkvb[192];        // nb @ qkv_w.T (folded LN bias)
__device__ float  g_biasf[8 * 2 * 8 * 32 * 4];  // [warp][mt][j][lane][e] rel-pos bias fragments

__global__ void prep_kernel(const float* __restrict__ qw, const float* __restrict__ pw,
                            const float* __restrict__ nw, const float* __restrict__ nb,
                            const float* __restrict__ rpb) {
    int idx = blockIdx.x * blockDim.x + threadIdx.x;   // 64 blocks * 256 = 16384
    if (idx < 12288) g_qkvw[idx] = __float2half(qw[idx] * nw[idx & 63]);
    if (idx < 4096)  g_projw[idx] = __float2half(pw[idx]);
    if (idx < 192) {
        float s = 0.f;
        #pragma unroll
        for (int c = 0; c < 64; c++) s += nb[c] * qw[idx * 64 + c];
        g_qkvb[idx] = s;
    }
    if (idx < 16384) {
        // decode [warp][mt][j][lane][e]
        int e    = idx & 3;
        int lane = (idx >> 2) & 31;
        int j    = (idx >> 7) & 7;
        int mt   = (idx >> 10) & 1;
        int warp = idx >> 11;
        int h  = warp >> 1;
        int m0 = (warp & 1) * 32;
        int g  = lane >> 2, tig = lane & 3;
        int rr = m0 + mt * 16 + g + ((e >> 1) << 3);
        int cc = j * 8 + tig * 2 + (e & 1);
        int dy = (rr >> 3) - (cc >> 3);
        int dx = (rr & 7) - (cc & 7);
        g_biasf[idx] = rpb[((dy + 7) * 15 + (dx + 7)) * 4 + h];
    }
}

__device__ __forceinline__ unsigned saddr(const void* p) {
    return (unsigned)__cvta_generic_to_shared(p);
}
__device__ __forceinline__ void ldsm_x4(unsigned a, unsigned& r0, unsigned& r1, unsigned& r2, unsigned& r3) {
    asm volatile("ldmatrix.sync.aligned.m8n8.x4.shared.b16 {%0,%1,%2,%3}, [%4];"
                 : "=r"(r0), "=r"(r1), "=r"(r2), "=r"(r3) : "r"(a));
}
__device__ __forceinline__ void ldsm_x2(unsigned a, unsigned& r0, unsigned& r1) {
    asm volatile("ldmatrix.sync.aligned.m8n8.x2.shared.b16 {%0,%1}, [%2];"
                 : "=r"(r0), "=r"(r1) : "r"(a));
}
__device__ __forceinline__ void ldsm_x2t(unsigned a, unsigned& r0, unsigned& r1) {
    asm volatile("ldmatrix.sync.aligned.m8n8.x2.trans.shared.b16 {%0,%1}, [%2];"
                 : "=r"(r0), "=r"(r1) : "r"(a));
}
__device__ __forceinline__ void mma16816(float c[4], unsigned a0, unsigned a1, unsigned a2, unsigned a3,
                                         unsigned b0, unsigned b1) {
    asm volatile("mma.sync.aligned.m16n8k16.row.col.f32.f16.f16.f32 "
                 "{%0,%1,%2,%3}, {%4,%5,%6,%7}, {%8,%9}, {%0,%1,%2,%3};"
                 : "+f"(c[0]), "+f"(c[1]), "+f"(c[2]), "+f"(c[3])
                 : "r"(a0), "r"(a1), "r"(a2), "r"(a3), "r"(b0), "r"(b1));
}
__device__ __forceinline__ unsigned packh2(float lo, float hi) {
    __half2 h = __floats2half2_rn(lo, hi);
    return *reinterpret_cast<unsigned*>(&h);
}

__global__ __launch_bounds__(256, 3)
void ewa_kernel(const float* __restrict__ x,
                const float* __restrict__ ascale,
                float* __restrict__ out) {
    extern __shared__ char smem[];
    __half* XN  = (__half*)(smem + OFF_XN);   // [64][72]  Z / AO
    __half* Wq  = (__half*)(smem + OFF_WQ);   // [192][72] / proj [64][72]
    __half* QKV = (__half*)(smem + OFF_QKV);  // [64][200]

    const int tid  = threadIdx.x;
    const int lane = tid & 31;
    const int warp = tid >> 5;
    const int g    = lane >> 2;
    const int tig  = lane & 3;
    const int l2   = lane & 15;

    const int win = blockIdx.x;
    const int b   = win >> 10;
    const int rem = win & 1023;
    const int wy  = rem >> 5;
    const int wx  = rem & 31;

    // ---- Phase 0: stage qkv weights (fp16) into smem ----
    #pragma unroll
    for (int i = tid; i < 1536; i += TPB) {
        int row = i >> 3, ck = i & 7;
        *(int4*)(Wq + row * 72 + ck * 8) = *(const int4*)(g_qkvw + row * 64 + ck * 8);
    }

    // ---- Phase 1: direct token-major load + in-register LayerNorm -> XN (fp16 Z) ----
    {
        int t = tid >> 2, q = tid & 3;            // token, channel quarter
        int pix = (wy * 8 + (t >> 3)) * 256 + wx * 8 + (t & 7);
        const float* base = x + (b * 64 + q * 16) * 65536 + pix;
        float v[16];
        #pragma unroll
        for (int i = 0; i < 16; i++) v[i] = base[i * 65536];
        float s = 0.f, ss = 0.f;
        #pragma unroll
        for (int i = 0; i < 16; i++) { s += v[i]; ss += v[i] * v[i]; }
        s  += __shfl_xor_sync(0xffffffffu, s, 1);  ss += __shfl_xor_sync(0xffffffffu, ss, 1);
        s  += __shfl_xor_sync(0xffffffffu, s, 2);  ss += __shfl_xor_sync(0xffffffffu, ss, 2);
        float mu   = s * (1.f / 64.f);
        float var  = ss * (1.f / 64.f) - mu * mu;
        float rstd = rsqrtf(var + 1e-5f);
        unsigned h8[8];
        #pragma unroll
        for (int i = 0; i < 8; i++)
            h8[i] = packh2((v[2 * i] - mu) * rstd, (v[2 * i + 1] - mu) * rstd);
        uint4* dst = (uint4*)(XN + t * 72 + q * 16);
        dst[0] = make_uint4(h8[0], h8[1], h8[2], h8[3]);
        dst[1] = make_uint4(h8[4], h8[5], h8[6], h8[7]);
    }
    __syncthreads();

    // ---- Phase 2: QKV GEMM  Z[64,64] @ Wq^T -> QKV[64,192] (+bias, q pre-scaled) ----
    {
        const int m0 = (warp & 1) * 32;
        const int n0 = (warp >> 1) * 48;
        float acc[2][6][4];
        #pragma unroll
        for (int mt = 0; mt < 2; mt++)
            #pragma unroll
            for (int j = 0; j < 6; j++)
                { acc[mt][j][0] = acc[mt][j][1] = acc[mt][j][2] = acc[mt][j][3] = 0.f; }
        #pragma unroll
        for (int kt = 0; kt < 4; kt++) {
            int k0 = kt * 16;
            unsigned a[2][4], bb[6][2];
            #pragma unroll
            for (int mt = 0; mt < 2; mt++)
                ldsm_x4(saddr(XN + (m0 + mt * 16 + l2) * 72 + k0 + (lane >> 4) * 8),
                        a[mt][0], a[mt][1], a[mt][2], a[mt][3]);
            #pragma unroll
            for (int j = 0; j < 6; j++)
                ldsm_x2(saddr(Wq + (n0 + j * 8 + (l2 & 7)) * 72 + k0 + (l2 >> 3) * 8),
                        bb[j][0], bb[j][1]);
            #pragma unroll
            for (int mt = 0; mt < 2; mt++)
                #pragma unroll
                for (int j = 0; j < 6; j++)
                    mma16816(acc[mt][j], a[mt][0], a[mt][1], a[mt][2], a[mt][3], bb[j][0], bb[j][1]);
        }
        #pragma unroll
        for (int j = 0; j < 6; j++) {
            int col = n0 + j * 8 + tig * 2;
            float2 bq = *(const float2*)(g_qkvb + col);
            float sc = (col < 64) ? 0.25f : 1.0f;    // hd^-0.5 folded into q
            #pragma unroll
            for (int mt = 0; mt < 2; mt++) {
                *(unsigned*)(QKV + (m0 + mt * 16 + g) * 200 + col) =
                    packh2((acc[mt][j][0] + bq.x) * sc, (acc[mt][j][1] + bq.y) * sc);
                *(unsigned*)(QKV + (m0 + mt * 16 + g + 8) * 200 + col) =
                    packh2((acc[mt][j][2] + bq.x) * sc, (acc[mt][j][3] + bq.y) * sc);
            }
        }
    }
    __syncthreads();

    // stage proj_w into (now free) Wq region; consumed after next sync
    #pragma unroll
    for (int i = tid; i < 512; i += TPB) {
        int row = i >> 3, ck = i & 7;
        *(int4*)(Wq + row * 72 + ck * 8) = *(const int4*)(g_projw + row * 64 + ck * 8);
    }

    // ---- Phase 3: attention. warp -> (head = warp>>1, rows m0=(warp&1)*32), mt sequential ----
    {
        const int h  = warp >> 1;
        const int m0 = (warp & 1) * 32;

        // hoist K fragments (shared across both mt iterations)
        unsigned kb[8][2];
        #pragma unroll
        for (int j = 0; j < 8; j++)
            ldsm_x2(saddr(QKV + (j * 8 + (l2 & 7)) * 200 + 64 + h * 16 + (l2 >> 3) * 8),
                    kb[j][0], kb[j][1]);

        #pragma unroll
        for (int mt = 0; mt < 2; mt++) {
            unsigned qa[4];
            ldsm_x4(saddr(QKV + (m0 + mt * 16 + l2) * 200 + h * 16 + (lane >> 4) * 8),
                    qa[0], qa[1], qa[2], qa[3]);

            float s[8][4];
            const float4* bf = (const float4*)(g_biasf) + ((warp * 2 + mt) * 8) * 32 + lane;
            float rmax[2] = {-1e30f, -1e30f};
            #pragma unroll
            for (int j = 0; j < 8; j++) {
                s[j][0] = s[j][1] = s[j][2] = s[j][3] = 0.f;
                mma16816(s[j], qa[0], qa[1], qa[2], qa[3], kb[j][0], kb[j][1]);
                float4 bv = bf[j * 32];
                s[j][0] += bv.x; s[j][1] += bv.y; s[j][2] += bv.z; s[j][3] += bv.w;
                rmax[0] = fmaxf(rmax[0], fmaxf(s[j][0], s[j][1]));
                rmax[1] = fmaxf(rmax[1], fmaxf(s[j][2], s[j][3]));
            }
            #pragma unroll
            for (int hh = 0; hh < 2; hh++) {
                float m_ = rmax[hh];
                m_ = fmaxf(m_, __shfl_xor_sync(0xffffffffu, m_, 1));
                m_ = fmaxf(m_, __shfl_xor_sync(0xffffffffu, m_, 2));
                rmax[hh] = m_;
            }
            float rsum[2] = {0.f, 0.f};
            #pragma unroll
            for (int j = 0; j < 8; j++) {
                s[j][0] = __expf(s[j][0] - rmax[0]);
                s[j][1] = __expf(s[j][1] - rmax[0]);
                s[j][2] = __expf(s[j][2] - rmax[1]);
                s[j][3] = __expf(s[j][3] - rmax[1]);
                rsum[0] += s[j][0] + s[j][1];
                rsum[1] += s[j][2] + s[j][3];
            }
            float inv[2];
            #pragma unroll
            for (int hh = 0; hh < 2; hh++) {
                float l = rsum[hh];
                l += __shfl_xor_sync(0xffffffffu, l, 1);
                l += __shfl_xor_sync(0xffffffffu, l, 2);
                inv[hh] = 1.f / l;
            }

            unsigned pa[4][4];
            #pragma unroll
            for (int kt = 0; kt < 4; kt++) {
                pa[kt][0] = packh2(s[2 * kt][0] * inv[0],     s[2 * kt][1] * inv[0]);
                pa[kt][1] = packh2(s[2 * kt][2] * inv[1],     s[2 * kt][3] * inv[1]);
                pa[kt][2] = packh2(s[2 * kt + 1][0] * inv[0], s[2 * kt + 1][1] * inv[0]);
                pa[kt][3] = packh2(s[2 * kt + 1][2] * inv[1], s[2 * kt + 1][3] * inv[1]);
            }

            float o[2][4];
            o[0][0] = o[0][1] = o[0][2] = o[0][3] = 0.f;
            o[1][0] = o[1][1] = o[1][2] = o[1][3] = 0.f;
            #pragma unroll
            for (int kt = 0; kt < 4; kt++)
                #pragma unroll
                for (int nt = 0; nt < 2; nt++) {
                    unsigned b0, b1;
                    ldsm_x2t(saddr(QKV + (kt * 16 + l2) * 200 + 128 + h * 16 + nt * 8), b0, b1);
                    mma16816(o[nt], pa[kt][0], pa[kt][1], pa[kt][2], pa[kt][3], b0, b1);
                }

            #pragma unroll
            for (int nt = 0; nt < 2; nt++) {
                int row = m0 + mt * 16 + g;
                int col = h * 16 + nt * 8 + tig * 2;
                *(unsigned*)(XN + row * 72 + col)       = packh2(o[nt][0], o[nt][1]);
                *(unsigned*)(XN + (row + 8) * 72 + col) = packh2(o[nt][2], o[nt][3]);
            }
        }
    }
    __syncthreads();

    // ---- Phase 4: proj GEMM [64,64]x[64,64] + residual + write out ----
    {
        const int m0 = (warp & 1) * 32;
        const int n0 = (warp >> 1) * 16;
        float acc[2][2][4];
        #pragma unroll
        for (int mt = 0; mt < 2; mt++)
            #pragma unroll
            for (int nt = 0; nt < 2; nt++)
                { acc[mt][nt][0] = acc[mt][nt][1] = acc[mt][nt][2] = acc[mt][nt][3] = 0.f; }
        #pragma unroll
        for (int kt = 0; kt < 4; kt++) {
            int k0 = kt * 16;
            unsigned a[2][4], bb[2][2];
            #pragma unroll
            for (int mt = 0; mt < 2; mt++)
                ldsm_x4(saddr(XN + (m0 + mt * 16 + l2) * 72 + k0 + (lane >> 4) * 8),
                        a[mt][0], a[mt][1], a[mt][2], a[mt][3]);
            #pragma unroll
            for (int nt = 0; nt < 2; nt++)
                ldsm_x2(saddr(Wq + (n0 + nt * 8 + (l2 & 7)) * 72 + k0 + (l2 >> 3) * 8),
                        bb[nt][0], bb[nt][1]);
            #pragma unroll
            for (int mt = 0; mt < 2; mt++)
                #pragma unroll
                for (int nt = 0; nt < 2; nt++)
                    mma16816(acc[mt][nt], a[mt][0], a[mt][1], a[mt][2], a[mt][3], bb[nt][0], bb[nt][1]);
        }
        float ssc = ascale[0];
        #pragma unroll
        for (int mt = 0; mt < 2; mt++)
            #pragma unroll
            for (int nt = 0; nt < 2; nt++)
                #pragma unroll
                for (int e = 0; e < 4; e++) {
                    int row = m0 + mt * 16 + g + ((e >> 1) << 3);   // token
                    int ch  = n0 + nt * 8 + tig * 2 + (e & 1);      // channel
                    int gi  = ((b * 64 + ch) * 256 + wy * 8 + (row >> 3)) * 256 + wx * 8 + (row & 7);
                    out[gi] = x[gi] + ssc * acc[mt][nt][e];
                }
    }
}

extern "C" void kernel_launch(void* const* d_in, const int* in_sizes, int n_in,
                              void* d_out, int out_size) {
    const float* x  = (const float*)d_in[0];
    const float* nw = (const float*)d_in[1];
    const float* nb = (const float*)d_in[2];
    const float* qw = (const float*)d_in[3];
    const float* pw = (const float*)d_in[4];
    const float* sc = (const float*)d_in[5];
    const float* rp = (const float*)d_in[6];
    float* out = (float*)d_out;

    cudaFuncSetAttribute(ewa_kernel, cudaFuncAttributeMaxDynamicSharedMemorySize, SMEM_BYTES);

    prep_kernel<<<64, 256>>>(qw, pw, nw, nb, rp);
    ewa_kernel<<<NWIN, TPB, SMEM_BYTES>>>(x, sc, out);
}

// round 3
// speedup vs baseline: 1.9537x; 1.3046x over previous
#include <cuda_runtime.h>
#include <cuda_fp16.h>

// Swin window attention, fully fused: one CTA per 8x8 window, 4 CTAs/SM.
// LN folded into pre-baked fp16 weight MMA-fragments (global, L1-hit);
// fp16 accumulators end-to-end; rel-pos bias pre-baked as half2 fragments.

#define NWIN   8192
#define TPB    256

// smem layout (bytes)
#define OFF_XN   0        // half [64][72]   9216  (LN output Z; later attn-out AO)
#define OFF_QKV  9216     // half [64][200] 25600
#define SMEM_BYTES 34816

// pre-baked tables (prep kernel fills these)
__device__ unsigned g_qkvfrag[3072 * 2];   // [ntile0..23][kt0..3][lane][2]  b0,b1 (LN+scale folded)
__device__ unsigned g_projfrag[1024 * 2];  // [ntile0..7][kt][lane][2]
__device__ unsigned g_qkvbh[96];           // half2 qkv bias per col-pair (scale folded)
__device__ unsigned g_biasfh[4096 * 2];    // [warp][mt][j][lane][2] rel-pos bias half2 frags

__device__ __forceinline__ unsigned packh2f(float lo, float hi) {
    __half2 h = __floats2half2_rn(lo, hi);
    return *reinterpret_cast<unsigned*>(&h);
}

__global__ void prep_kernel(const float* __restrict__ qw, const float* __restrict__ pw,
                            const float* __restrict__ nw, const float* __restrict__ nb,
                            const float* __restrict__ rpb) {
    int idx = blockIdx.x * blockDim.x + threadIdx.x;   // 32 blocks * 256 = 8192

    if (idx < 3072) {  // qkv weight fragments (norm_w + q-scale folded)
        int lane = idx & 31, kt = (idx >> 5) & 3, ntile = idx >> 7;
        int n  = ntile * 8 + (lane >> 2);
        int k0 = kt * 16 + (lane & 3) * 2;
        float sc = (n < 64) ? 0.25f : 1.0f;
        const float* wr = qw + n * 64;
        g_qkvfrag[idx * 2 + 0] = packh2f(wr[k0] * nw[k0] * sc,     wr[k0 + 1] * nw[k0 + 1] * sc);
        g_qkvfrag[idx * 2 + 1] = packh2f(wr[k0 + 8] * nw[k0 + 8] * sc, wr[k0 + 9] * nw[k0 + 9] * sc);
    }
    if (idx < 1024) {  // proj weight fragments
        int lane = idx & 31, kt = (idx >> 5) & 3, ntile = idx >> 7;
        int n  = ntile * 8 + (lane >> 2);
        int k0 = kt * 16 + (lane & 3) * 2;
        const float* wr = pw + n * 64;
        g_projfrag[idx * 2 + 0] = packh2f(wr[k0],     wr[k0 + 1]);
        g_projfrag[idx * 2 + 1] = packh2f(wr[k0 + 8], wr[k0 + 9]);
    }
    if (idx < 96) {    // folded LN-bias through qkv (per output col pair), scale folded
        float b0 = 0.f, b1 = 0.f;
        int c = idx * 2;
        for (int k = 0; k < 64; k++) {
            b0 += nb[k] * qw[c * 64 + k];
            b1 += nb[k] * qw[(c + 1) * 64 + k];
        }
        float sc = (c < 64) ? 0.25f : 1.0f;
        g_qkvbh[idx] = packh2f(b0 * sc, b1 * sc);
    }
    if (idx < 4096) {  // rel-pos bias fragments (half2), layout [warp][mt][j][lane][2]
        int lane = idx & 31, j = (idx >> 5) & 7, mt = (idx >> 8) & 1, warp = idx >> 9;
        int h  = warp >> 1;
        int m0 = (warp & 1) * 32;
        int g  = lane >> 2, tig = lane & 3;
        int rr = m0 + mt * 16 + g;
        int cc = j * 8 + tig * 2;
        auto bias = [&](int r, int c) {
            int dy = (r >> 3) - (c >> 3);
            int dx = (r & 7) - (c & 7);
            return rpb[((dy + 7) * 15 + (dx + 7)) * 4 + h];
        };
        g_biasfh[idx * 2 + 0] = packh2f(bias(rr, cc),     bias(rr, cc + 1));
        g_biasfh[idx * 2 + 1] = packh2f(bias(rr + 8, cc), bias(rr + 8, cc + 1));
    }
}

__device__ __forceinline__ unsigned saddr(const void* p) {
    return (unsigned)__cvta_generic_to_shared(p);
}
__device__ __forceinline__ void ldsm_x4(unsigned a, unsigned& r0, unsigned& r1, unsigned& r2, unsigned& r3) {
    asm volatile("ldmatrix.sync.aligned.m8n8.x4.shared.b16 {%0,%1,%2,%3}, [%4];"
                 : "=r"(r0), "=r"(r1), "=r"(r2), "=r"(r3) : "r"(a));
}
__device__ __forceinline__ void ldsm_x2(unsigned a, unsigned& r0, unsigned& r1) {
    asm volatile("ldmatrix.sync.aligned.m8n8.x2.shared.b16 {%0,%1}, [%2];"
                 : "=r"(r0), "=r"(r1) : "r"(a));
}
__device__ __forceinline__ void ldsm_x2t(unsigned a, unsigned& r0, unsigned& r1) {
    asm volatile("ldmatrix.sync.aligned.m8n8.x2.trans.shared.b16 {%0,%1}, [%2];"
                 : "=r"(r0), "=r"(r1) : "r"(a));
}
// fp16-accumulator MMA
__device__ __forceinline__ void mmah(uint2& c, unsigned a0, unsigned a1, unsigned a2, unsigned a3,
                                     unsigned b0, unsigned b1) {
    asm volatile("mma.sync.aligned.m16n8k16.row.col.f16.f16.f16.f16 "
                 "{%0,%1}, {%2,%3,%4,%5}, {%6,%7}, {%0,%1};"
                 : "+r"(c.x), "+r"(c.y)
                 : "r"(a0), "r"(a1), "r"(a2), "r"(a3), "r"(b0), "r"(b1));
}
__device__ __forceinline__ unsigned hadd2u(unsigned a, unsigned b) {
    __half2 r = __hadd2(*(__half2*)&a, *(__half2*)&b);
    return *(unsigned*)&r;
}
__device__ __forceinline__ unsigned hmul2u(unsigned a, unsigned b) {
    __half2 r = __hmul2(*(__half2*)&a, *(__half2*)&b);
    return *(unsigned*)&r;
}
__device__ __forceinline__ float2 h2f2(unsigned u) {
    return __half22float2(*(__half2*)&u);
}

__global__ __launch_bounds__(256, 4)
void ewa_kernel(const float* __restrict__ x,
                const float* __restrict__ ascale,
                float* __restrict__ out) {
    extern __shared__ char smem[];
    __half* XN  = (__half*)(smem + OFF_XN);   // [64][72]  Z / AO
    __half* QKV = (__half*)(smem + OFF_QKV);  // [64][200]

    const int tid  = threadIdx.x;
    const int lane = tid & 31;
    const int warp = tid >> 5;
    const int g    = lane >> 2;
    const int tig  = lane & 3;
    const int l2   = lane & 15;

    const int win = blockIdx.x;
    const int b   = win >> 10;
    const int rem = win & 1023;
    const int wy  = rem >> 5;
    const int wx  = rem & 31;

    // ---- Phase 1: direct token-major load + in-register LayerNorm -> XN (fp16 Z) ----
    {
        int t = tid >> 2, q = tid & 3;            // token, channel quarter
        int pix = (wy * 8 + (t >> 3)) * 256 + wx * 8 + (t & 7);
        const float* base = x + (b * 64 + q * 16) * 65536 + pix;
        float v[16];
        #pragma unroll
        for (int i = 0; i < 16; i++) v[i] = base[i * 65536];
        float s = 0.f, ss = 0.f;
        #pragma unroll
        for (int i = 0; i < 16; i++) { s += v[i]; ss += v[i] * v[i]; }
        s  += __shfl_xor_sync(0xffffffffu, s, 1);  ss += __shfl_xor_sync(0xffffffffu, ss, 1);
        s  += __shfl_xor_sync(0xffffffffu, s, 2);  ss += __shfl_xor_sync(0xffffffffu, ss, 2);
        float mu   = s * (1.f / 64.f);
        float var  = ss * (1.f / 64.f) - mu * mu;
        float rstd = rsqrtf(var + 1e-5f);
        unsigned h8[8];
        #pragma unroll
        for (int i = 0; i < 8; i++)
            h8[i] = packh2f((v[2 * i] - mu) * rstd, (v[2 * i + 1] - mu) * rstd);
        uint4* dst = (uint4*)(XN + t * 72 + q * 16);
        dst[0] = make_uint4(h8[0], h8[1], h8[2], h8[3]);
        dst[1] = make_uint4(h8[4], h8[5], h8[6], h8[7]);
    }
    __syncthreads();

    // ---- Phase 2: QKV GEMM  Z[64,64] @ W^T -> QKV[64,192]  (fp16 acc, B frags from global) ----
    {
        const int m0 = (warp & 1) * 32;
        const int nt0 = (warp >> 1) * 6;          // ntile base
        uint2 acc[2][6];
        #pragma unroll
        for (int mt = 0; mt < 2; mt++)
            #pragma unroll
            for (int j = 0; j < 6; j++) { acc[mt][j].x = 0u; acc[mt][j].y = 0u; }
        #pragma unroll
        for (int kt = 0; kt < 4; kt++) {
            unsigned a[2][4];
            #pragma unroll
            for (int mt = 0; mt < 2; mt++)
                ldsm_x4(saddr(XN + (m0 + mt * 16 + l2) * 72 + kt * 16 + (lane >> 4) * 8),
                        a[mt][0], a[mt][1], a[mt][2], a[mt][3]);
            uint2 bf[6];
            #pragma unroll
            for (int j = 0; j < 6; j++)
                bf[j] = *(const uint2*)(g_qkvfrag + (((nt0 + j) * 4 + kt) * 32 + lane) * 2);
            #pragma unroll
            for (int mt = 0; mt < 2; mt++)
                #pragma unroll
                for (int j = 0; j < 6; j++)
                    mmah(acc[mt][j], a[mt][0], a[mt][1], a[mt][2], a[mt][3], bf[j].x, bf[j].y);
        }
        #pragma unroll
        for (int j = 0; j < 6; j++) {
            int col = (nt0 + j) * 8 + tig * 2;
            unsigned bh = g_qkvbh[(nt0 + j) * 4 + tig];
            #pragma unroll
            for (int mt = 0; mt < 2; mt++) {
                int row = m0 + mt * 16 + g;
                *(unsigned*)(QKV + row * 200 + col)       = hadd2u(acc[mt][j].x, bh);
                *(unsigned*)(QKV + (row + 8) * 200 + col) = hadd2u(acc[mt][j].y, bh);
            }
        }
    }
    __syncthreads();

    // ---- Phase 3: attention. warp -> (head = warp>>1, rows m0=(warp&1)*32) ----
    {
        const int h  = warp >> 1;
        const int m0 = (warp & 1) * 32;

        unsigned kb[8][2];
        #pragma unroll
        for (int j = 0; j < 8; j++)
            ldsm_x2(saddr(QKV + (j * 8 + (l2 & 7)) * 200 + 64 + h * 16 + (l2 >> 3) * 8),
                    kb[j][0], kb[j][1]);

        #pragma unroll
        for (int mt = 0; mt < 2; mt++) {
            unsigned qa[4];
            ldsm_x4(saddr(QKV + (m0 + mt * 16 + l2) * 200 + h * 16 + (lane >> 4) * 8),
                    qa[0], qa[1], qa[2], qa[3]);

            uint2 s[8];
            #pragma unroll
            for (int j = 0; j < 8; j++) { s[j].x = 0u; s[j].y = 0u; }
            #pragma unroll
            for (int j = 0; j < 8; j++)
                mmah(s[j], qa[0], qa[1], qa[2], qa[3], kb[j][0], kb[j][1]);

            const uint2* bfh = (const uint2*)(g_biasfh) + ((warp * 2 + mt) * 8) * 32 + lane;
            float mx0 = -1e30f, mx1 = -1e30f;
            #pragma unroll
            for (int j = 0; j < 8; j++) {
                uint2 bv = bfh[j * 32];
                s[j].x = hadd2u(s[j].x, bv.x);
                s[j].y = hadd2u(s[j].y, bv.y);
                float2 f0 = h2f2(s[j].x);
                float2 f1 = h2f2(s[j].y);
                mx0 = fmaxf(mx0, fmaxf(f0.x, f0.y));
                mx1 = fmaxf(mx1, fmaxf(f1.x, f1.y));
            }
            mx0 = fmaxf(mx0, __shfl_xor_sync(0xffffffffu, mx0, 1));
            mx0 = fmaxf(mx0, __shfl_xor_sync(0xffffffffu, mx0, 2));
            mx1 = fmaxf(mx1, __shfl_xor_sync(0xffffffffu, mx1, 1));
            mx1 = fmaxf(mx1, __shfl_xor_sync(0xffffffffu, mx1, 2));

            float sum0 = 0.f, sum1 = 0.f;
            #pragma unroll
            for (int j = 0; j < 8; j++) {
                float2 f0 = h2f2(s[j].x);
                float2 f1 = h2f2(s[j].y);
                float e0 = __expf(f0.x - mx0), e1 = __expf(f0.y - mx0);
                float e2 = __expf(f1.x - mx1), e3 = __expf(f1.y - mx1);
                sum0 += e0 + e1;  sum1 += e2 + e3;
                s[j].x = packh2f(e0, e1);
                s[j].y = packh2f(e2, e3);
            }
            sum0 += __shfl_xor_sync(0xffffffffu, sum0, 1);
            sum0 += __shfl_xor_sync(0xffffffffu, sum0, 2);
            sum1 += __shfl_xor_sync(0xffffffffu, sum1, 1);
            sum1 += __shfl_xor_sync(0xffffffffu, sum1, 2);

            // AV with unnormalized probs; normalize output after (linearity)
            uint2 o[2];
            o[0].x = o[0].y = o[1].x = o[1].y = 0u;
            #pragma unroll
            for (int kt = 0; kt < 4; kt++)
                #pragma unroll
                for (int nt = 0; nt < 2; nt++) {
                    unsigned v0, v1;
                    ldsm_x2t(saddr(QKV + (kt * 16 + l2) * 200 + 128 + h * 16 + nt * 8), v0, v1);
                    mmah(o[nt], s[2 * kt].x, s[2 * kt].y, s[2 * kt + 1].x, s[2 * kt + 1].y, v0, v1);
                }
            unsigned i0 = packh2f(1.f / sum0, 1.f / sum0);
            unsigned i1 = packh2f(1.f / sum1, 1.f / sum1);
            #pragma unroll
            for (int nt = 0; nt < 2; nt++) {
                int row = m0 + mt * 16 + g;
                int col = h * 16 + nt * 8 + tig * 2;
                *(unsigned*)(XN + row * 72 + col)       = hmul2u(o[nt].x, i0);
                *(unsigned*)(XN + (row + 8) * 72 + col) = hmul2u(o[nt].y, i1);
            }
        }
    }
    __syncthreads();

    // ---- Phase 4: proj GEMM [64,64]x[64,64] + residual + write out (fp16 acc) ----
    {
        const int m0  = (warp & 1) * 32;
        const int ntb = (warp >> 1) * 2;      // ntile base (8-col tiles)
        uint2 acc[2][2];
        acc[0][0].x = acc[0][0].y = acc[0][1].x = acc[0][1].y = 0u;
        acc[1][0].x = acc[1][0].y = acc[1][1].x = acc[1][1].y = 0u;
        #pragma unroll
        for (int kt = 0; kt < 4; kt++) {
            unsigned a[2][4];
            #pragma unroll
            for (int mt = 0; mt < 2; mt++)
                ldsm_x4(saddr(XN + (m0 + mt * 16 + l2) * 72 + kt * 16 + (lane >> 4) * 8),
                        a[mt][0], a[mt][1], a[mt][2], a[mt][3]);
            uint2 bf[2];
            #pragma unroll
            for (int nt = 0; nt < 2; nt++)
                bf[nt] = *(const uint2*)(g_projfrag + (((ntb + nt) * 4 + kt) * 32 + lane) * 2);
            #pragma unroll
            for (int mt = 0; mt < 2; mt++)
                #pragma unroll
                for (int nt = 0; nt < 2; nt++)
                    mmah(acc[mt][nt], a[mt][0], a[mt][1], a[mt][2], a[mt][3], bf[nt].x, bf[nt].y);
        }
        float ssc = ascale[0];
        #pragma unroll
        for (int mt = 0; mt < 2; mt++)
            #pragma unroll
            for (int nt = 0; nt < 2; nt++) {
                int ch = (ntb + nt) * 8 + tig * 2;
                float2 lo = h2f2(acc[mt][nt].x);   // rows m0+mt*16+g
                float2 hi = h2f2(acc[mt][nt].y);   // rows +8
                #pragma unroll
                for (int half = 0; half < 2; half++) {
                    int row = m0 + mt * 16 + g + half * 8;
                    float2 v = half ? hi : lo;
                    int gi0 = ((b * 64 + ch) * 256 + wy * 8 + (row >> 3)) * 256 + wx * 8 + (row & 7);
                    int gi1 = gi0 + 65536;   // ch+1
                    out[gi0] = x[gi0] + ssc * v.x;
                    out[gi1] = x[gi1] + ssc * v.y;
                }
            }
    }
}

extern "C" void kernel_launch(void* const* d_in, const int* in_sizes, int n_in,
                              void* d_out, int out_size) {
    const float* x  = (const float*)d_in[0];
    const float* nw = (const float*)d_in[1];
    const float* nb = (const float*)d_in[2];
    const float* qw = (const float*)d_in[3];
    const float* pw = (const float*)d_in[4];
    const float* sc = (const float*)d_in[5];
    const float* rp = (const float*)d_in[6];
    float* out = (float*)d_out;

    cudaFuncSetAttribute(ewa_kernel, cudaFuncAttributeMaxDynamicSharedMemorySize, SMEM_BYTES);

    prep_kernel<<<32, 256>>>(qw, pw, nw, nb, rp);
    ewa_kernel<<<NWIN, TPB, SMEM_BYTES>>>(x, sc, out);
}